// round 3
// baseline (speedup 1.0000x reference)
#include <cuda_runtime.h>
#include <cstdint>

#define NN 200000
#define EE 4000000
#define RR 4
#define DD 64
#define GG 64
#define CC 10

// ---- scratch (device globals: allocation-free rule) ----
__device__ float g_h0[NN * DD];            // 51.2 MB
__device__ float g_h1[NN * DD];            // 51.2 MB
__device__ float g_trans[NN * RR * DD];    // 204.8 MB  [N][R*64]
__device__ int   g_cnt[NN * RR];
__device__ float g_inv[NN * RR];
__device__ int   g_bcnt[GG];
__device__ float g_binv[GG];
__device__ float g_pool[GG * DD];

static __device__ __forceinline__ float4 ld4(const float* p) {
    return *reinterpret_cast<const float4*>(p);
}

// ---------------- setup kernels ----------------

__global__ void k_count_edges(const int* __restrict__ tgt, const int* __restrict__ et) {
    int e = blockIdx.x * blockDim.x + threadIdx.x;
    if (e < EE) atomicAdd(&g_cnt[tgt[e] * RR + et[e]], 1);
}

__global__ void k_count_batch(const int* __restrict__ batch) {
    int n = blockIdx.x * blockDim.x + threadIdx.x;
    unsigned act = __ballot_sync(0xffffffffu, n < NN);
    if (n < NN) {
        int g = batch[n];
        unsigned m = __match_any_sync(act, g);
        int leader = __ffs(m) - 1;
        if ((threadIdx.x & 31) == leader) atomicAdd(&g_bcnt[g], __popc(m));
    }
}

__global__ void k_invert() {
    int i = blockIdx.x * blockDim.x + threadIdx.x;
    if (i < NN * RR) {
        int c = g_cnt[i];
        g_inv[i] = 1.0f / (float)(c > 0 ? c : 1);
    }
    if (i < GG) {
        int c = g_bcnt[i];
        g_binv[i] = 1.0f / (float)(c > 0 ? c : 1);
    }
}

__global__ void k_embed(const int* __restrict__ x_op, const int* __restrict__ x_cat,
                        const float* __restrict__ op_emb, const float* __restrict__ cat_emb) {
    int idx = blockIdx.x * blockDim.x + threadIdx.x;   // over NN*16 float4s
    if (idx >= NN * 16) return;
    int n = idx >> 4, q = idx & 15;
    float4 a = ld4(op_emb + (size_t)x_op[n] * DD + q * 4);
    float4 b = ld4(cat_emb + (size_t)x_cat[n] * DD + q * 4);
    float4 o;
    o.x = a.x + b.x; o.y = a.y + b.y; o.z = a.z + b.z; o.w = a.w + b.w;
    *reinterpret_cast<float4*>(g_h0 + (size_t)idx * 4) = o;
}

// ---------------- fused transform GEMM ----------------
// Per layer:  C[n, 0:256]  = relu_in(hin[n]) @ Wcat   -> g_trans   (Wcat[k, r*64+j] = w[r,k,j])
//             C[n,256:320] = relu_in(hin[n]) @ root + bias -> hout (accumulator init)
// [64-node tile] x [K=64] x [320 cols]. 512 threads: (c=tid&15) x (nz=tid>>4, 0..31).
// Thread: 2 nodes (nz*2, nz*2+1) x 10 column-pairs (2*(c+16p), p=0..9).
// A pre-duplicated in smem as f32x2 {a,a} so LDS.64 feeds fma.rn.f32x2 directly.

#define SMEM_GEMM (64 * 320 * 4 + 64 * 64 * 8)   // sW 80KB + sAdup 32KB = 112KB

static __device__ __forceinline__ void ffma2(unsigned long long& acc,
                                             unsigned long long a, unsigned long long b) {
    asm("fma.rn.f32x2 %0, %1, %2, %0;" : "+l"(acc) : "l"(a), "l"(b));
}

__global__ void __launch_bounds__(512, 1)
k_trans(const float* __restrict__ hin,
        const float* __restrict__ w, const float* __restrict__ root,
        const float* __restrict__ bias,
        float* __restrict__ hout, int relu_in) {
    extern __shared__ float sm[];
    float* sW = sm;                                        // [64][320]
    unsigned long long* sA = (unsigned long long*)(sm + 64 * 320);  // [64][64] dup pairs
    int tid = threadIdx.x;
    int n0 = blockIdx.x * 64;

    // stage W: sW[k][r*64+j] = w[r,k,j]; sW[k][256+j] = root[k,j]
#pragma unroll
    for (int i = tid; i < 64 * 80; i += 512) {
        int k = i / 80, c4 = (i % 80) * 4;
        float4 v;
        if (c4 < 256) {
            int r = c4 >> 6, j = c4 & 63;
            v = ld4(w + (size_t)r * 4096 + k * 64 + j);
        } else {
            v = ld4(root + (size_t)k * 64 + (c4 - 256));
        }
        *reinterpret_cast<float4*>(&sW[k * 320 + c4]) = v;
    }
    // stage A duplicated: sA[n][k] = {a, a}
#pragma unroll
    for (int i = tid; i < 64 * 64; i += 512) {
        int nl = i >> 6, k = i & 63;
        float a = hin[(size_t)(n0 + nl) * 64 + k];
        if (relu_in) a = fmaxf(a, 0.f);
        unsigned long long aa;
        asm("mov.b64 %0, {%1, %1};" : "=l"(aa) : "f"(a));
        sA[nl * 64 + k] = aa;
    }
    __syncthreads();

    int c  = tid & 15;
    int nz = tid >> 4;                                     // 0..31
    const unsigned long long* sW64 = (const unsigned long long*)sW;  // [64][160]

    unsigned long long acc[2][10];
#pragma unroll
    for (int i = 0; i < 2; i++)
#pragma unroll
        for (int p = 0; p < 10; p++) acc[i][p] = 0ull;

#pragma unroll 4
    for (int k = 0; k < 64; k++) {
        unsigned long long b[10];
#pragma unroll
        for (int p = 0; p < 10; p++) b[p] = sW64[k * 160 + c + p * 16];
#pragma unroll
        for (int i = 0; i < 2; i++) {
            unsigned long long a = sA[(nz * 2 + i) * 64 + k];
#pragma unroll
            for (int p = 0; p < 10; p++) ffma2(acc[i][p], a, b[p]);
        }
    }

#pragma unroll
    for (int i = 0; i < 2; i++) {
        int n = n0 + nz * 2 + i;
#pragma unroll
        for (int p = 0; p < 10; p++) {
            int col = 2 * (c + p * 16);           // 0..318
            float2 f;
            asm("mov.b64 {%0, %1}, %2;" : "=f"(f.x), "=f"(f.y) : "l"(acc[i][p]));
            if (col < 256) {
                *reinterpret_cast<float2*>(g_trans + (size_t)n * 256 + col) = f;
            } else {
                int j = col - 256;
                f.x += bias[j]; f.y += bias[j + 1];
                *reinterpret_cast<float2*>(hout + (size_t)n * 64 + j) = f;
            }
        }
    }
}

// ---------------- scatter: hout[t] += trans[src, r, :] * inv[t,r] ----------------
// 16 lanes per edge; leader lane loads indices, shfl-broadcast to the group.
// red.v4 targets the 51MB (L2-resident) hout buffer.

__global__ void k_scatter(const int* __restrict__ src, const int* __restrict__ tgt,
                          const int* __restrict__ et, float* __restrict__ hout) {
    int gid = blockIdx.x * blockDim.x + threadIdx.x;
    int e = gid >> 4;
    int lane = gid & 15;
    // EE*16 is an exact multiple of blockDim: no ragged tail, full warps active.
    int s = 0, t = 0, r = 0;
    float sc = 0.f;
    if (lane == 0) {
        s = __ldg(src + e);
        t = __ldg(tgt + e);
        r = __ldg(et + e);
        sc = __ldg(g_inv + t * RR + r);
    }
    s  = __shfl_sync(0xffffffffu, s, 0, 16);
    t  = __shfl_sync(0xffffffffu, t, 0, 16);
    r  = __shfl_sync(0xffffffffu, r, 0, 16);
    sc = __shfl_sync(0xffffffffu, sc, 0, 16);

    float4 v = ld4(g_trans + (size_t)s * 256 + r * 64 + lane * 4);
    v.x *= sc; v.y *= sc; v.z *= sc; v.w *= sc;
    float* dst = hout + (size_t)t * DD + lane * 4;
    asm volatile("red.global.add.v4.f32 [%0], {%1,%2,%3,%4};"
                 :: "l"(dst), "f"(v.x), "f"(v.y), "f"(v.z), "f"(v.w) : "memory");
}

// ---------------- mean pool (batch is sorted; layer-3 output has no relu) ----------------

__global__ void k_pool(const float* __restrict__ h, const int* __restrict__ batch) {
    int d = threadIdx.x;                         // 64
    int row = threadIdx.y;                       // 4
    int base = (blockIdx.x * 4 + row) * 512;
    int gcur = -1;
    float acc = 0.f;
    for (int i = 0; i < 512; i++) {
        int n = base + i;
        if (n >= NN) break;
        int g = __ldg(batch + n);
        if (g != gcur) {
            if (gcur >= 0) atomicAdd(&g_pool[gcur * DD + d], acc);
            acc = 0.f; gcur = g;
        }
        acc += h[(size_t)n * DD + d];
    }
    if (gcur >= 0) atomicAdd(&g_pool[gcur * DD + d], acc);
}

// ---------------- head: fc1+relu, fc2, log_softmax ----------------

__global__ void k_head(const float* __restrict__ fc1w, const float* __restrict__ fc1b,
                       const float* __restrict__ fc2w, const float* __restrict__ fc2b,
                       float* __restrict__ out) {
    int g = blockIdx.x;
    int tid = threadIdx.x;   // 64
    __shared__ float p[64], t[64], lg[10], lse;
    p[tid] = g_pool[g * DD + tid] * g_binv[g];
    __syncthreads();
    float s = fc1b[tid];
#pragma unroll 8
    for (int k = 0; k < 64; k++) s += p[k] * fc1w[k * 64 + tid];
    t[tid] = fmaxf(s, 0.f);
    __syncthreads();
    if (tid < CC) {
        float s2 = fc2b[tid];
#pragma unroll 8
        for (int k = 0; k < 64; k++) s2 += t[k] * fc2w[k * CC + tid];
        lg[tid] = s2;
    }
    __syncthreads();
    if (tid == 0) {
        float m = lg[0];
        for (int c2 = 1; c2 < CC; c2++) m = fmaxf(m, lg[c2]);
        float se = 0.f;
        for (int c2 = 0; c2 < CC; c2++) se += expf(lg[c2] - m);
        lse = m + logf(se);
    }
    __syncthreads();
    if (tid < CC) out[g * CC + tid] = lg[tid] - lse;
}

// ---------------- launch ----------------

extern "C" void kernel_launch(void* const* d_in, const int* in_sizes, int n_in,
                              void* d_out, int out_size) {
    const int*   x_op    = (const int*)d_in[0];
    const int*   x_cat   = (const int*)d_in[1];
    const int*   eidx    = (const int*)d_in[2];
    const int*   etype   = (const int*)d_in[3];
    const int*   batch   = (const int*)d_in[4];
    const float* op_emb  = (const float*)d_in[5];
    const float* cat_emb = (const float*)d_in[6];
    const float* W[3]    = { (const float*)d_in[7],  (const float*)d_in[10], (const float*)d_in[13] };
    const float* Rt[3]   = { (const float*)d_in[8],  (const float*)d_in[11], (const float*)d_in[14] };
    const float* B[3]    = { (const float*)d_in[9],  (const float*)d_in[12], (const float*)d_in[15] };
    const float* fc1w    = (const float*)d_in[16];
    const float* fc1b    = (const float*)d_in[17];
    const float* fc2w    = (const float*)d_in[18];
    const float* fc2b    = (const float*)d_in[19];
    float* out = (float*)d_out;

    const int* src = eidx;
    const int* tgt = eidx + EE;

    void *p_cnt, *p_bcnt, *p_pool, *p0, *p1;
    cudaGetSymbolAddress(&p_cnt, g_cnt);
    cudaGetSymbolAddress(&p_bcnt, g_bcnt);
    cudaGetSymbolAddress(&p_pool, g_pool);
    cudaGetSymbolAddress(&p0, g_h0);
    cudaGetSymbolAddress(&p1, g_h1);
    float* hbuf[2] = { (float*)p0, (float*)p1 };

    cudaFuncSetAttribute(k_trans, cudaFuncAttributeMaxDynamicSharedMemorySize, SMEM_GEMM);

    cudaMemsetAsync(p_cnt, 0, sizeof(int) * NN * RR, 0);
    cudaMemsetAsync(p_bcnt, 0, sizeof(int) * GG, 0);
    cudaMemsetAsync(p_pool, 0, sizeof(float) * GG * DD, 0);

    k_count_edges<<<(EE + 255) / 256, 256>>>(tgt, etype);
    k_count_batch<<<(NN + 255) / 256, 256>>>(batch);
    k_invert<<<(NN * RR + 255) / 256, 256>>>();
    k_embed<<<(NN * 16 + 255) / 256, 256>>>(x_op, x_cat, op_emb, cat_emb);

    for (int l = 0; l < 3; l++) {
        const float* hin = hbuf[l & 1];
        float* hout = hbuf[(l + 1) & 1];
        // GEMM writes g_trans AND initializes hout with root transform + bias
        k_trans<<<NN / 64, 512, SMEM_GEMM>>>(hin, W[l], Rt[l], B[l], hout, l > 0 ? 1 : 0);
        // edge scatter accumulates mean-scaled messages into hout (L2-resident)
        k_scatter<<<(EE * 16) / 256, 256>>>(src, tgt, etype, hout);
    }

    k_pool<<<(NN + 2047) / 2048, dim3(64, 4)>>>(hbuf[1], batch);
    k_head<<<GG, 64>>>(fc1w, fc1b, fc2w, fc2b, out);
}

// round 9
// speedup vs baseline: 1.0018x; 1.0018x over previous
#include <cuda_runtime.h>
#include <cstdint>

#define NN 200000
#define EE 4000000
#define RR 4
#define DD 64
#define GG 64
#define CC 10

// ---- scratch (device globals: allocation-free rule) ----
__device__ float    g_h0[NN * DD];            // 51.2 MB
__device__ float    g_h1[NN * DD];            // 51.2 MB
__device__ unsigned g_transb[NN * RR * 32];   // 102.4 MB  bf16x2 pairs: [n][r*32+pair]
__device__ int      g_cnt[NN * RR];
__device__ float    g_inv[NN * RR];
__device__ int      g_off[NN * RR];           // CSR bucket offsets
__device__ int      g_fcnt[NN * RR];          // fill cursors
__device__ int      g_esrc[EE];               // CSR edge src lists (16 MB)
__device__ int      g_total;                  // offset allocator
__device__ int      g_bcnt[GG];
__device__ float    g_binv[GG];
__device__ float    g_pool[GG * DD];

static __device__ __forceinline__ float4 ld4(const float* p) {
    return *reinterpret_cast<const float4*>(p);
}

// ---------------- setup kernels ----------------

__global__ void k_count_edges(const int* __restrict__ tgt, const int* __restrict__ et) {
    int e = blockIdx.x * blockDim.x + threadIdx.x;
    if (e < EE) atomicAdd(&g_cnt[tgt[e] * RR + et[e]], 1);
}

__global__ void k_count_batch(const int* __restrict__ batch) {
    int n = blockIdx.x * blockDim.x + threadIdx.x;
    unsigned act = __ballot_sync(0xffffffffu, n < NN);
    if (n < NN) {
        int g = batch[n];
        unsigned m = __match_any_sync(act, g);
        int leader = __ffs(m) - 1;
        if ((threadIdx.x & 31) == leader) atomicAdd(&g_bcnt[g], __popc(m));
    }
}

// Disjoint bucket ranges via block-aggregated atomic allocation.
// (Bucket placement is run-order dependent but ranges are disjoint; only the
//  fp32 summation order changes, well inside tolerance.)
__global__ void k_offsets() {
    int tid = threadIdx.x;
    int i = blockIdx.x * 256 + tid;           // 3125*256 == NN*RR exactly
    int lane = tid & 31, wid = tid >> 5;
    int c = g_cnt[i];
    int x = c;
#pragma unroll
    for (int d = 1; d < 32; d <<= 1) {
        int y = __shfl_up_sync(0xffffffffu, x, d);
        if (lane >= d) x += y;
    }
    __shared__ int wsum[8];
    __shared__ int sbase;
    if (lane == 31) wsum[wid] = x;
    __syncthreads();
    if (tid < 8) {
        int w = wsum[tid];
#pragma unroll
        for (int d = 1; d < 8; d <<= 1) {
            int y = __shfl_up_sync(0xffu, w, d);
            if (tid >= d) w += y;
        }
        wsum[tid] = w;                        // inclusive warp-sum scan
    }
    __syncthreads();
    if (tid == 0) sbase = atomicAdd(&g_total, wsum[7]);
    __syncthreads();
    int wprev = (wid == 0) ? 0 : wsum[wid - 1];
    g_off[i] = sbase + wprev + x - c;         // exclusive within block + base
}

__global__ void k_fill(const int* __restrict__ src, const int* __restrict__ tgt,
                       const int* __restrict__ et) {
    int e = blockIdx.x * blockDim.x + threadIdx.x;
    if (e >= EE) return;
    int b = tgt[e] * RR + et[e];
    int pos = g_off[b] + atomicAdd(&g_fcnt[b], 1);
    g_esrc[pos] = src[e];
}

__global__ void k_invert() {
    int i = blockIdx.x * blockDim.x + threadIdx.x;
    if (i < NN * RR) {
        int c = g_cnt[i];
        g_inv[i] = 1.0f / (float)(c > 0 ? c : 1);
    }
    if (i < GG) {
        int c = g_bcnt[i];
        g_binv[i] = 1.0f / (float)(c > 0 ? c : 1);
    }
}

__global__ void k_embed(const int* __restrict__ x_op, const int* __restrict__ x_cat,
                        const float* __restrict__ op_emb, const float* __restrict__ cat_emb) {
    int idx = blockIdx.x * blockDim.x + threadIdx.x;   // over NN*16 float4s
    if (idx >= NN * 16) return;
    int n = idx >> 4, q = idx & 15;
    float4 a = ld4(op_emb + (size_t)x_op[n] * DD + q * 4);
    float4 b = ld4(cat_emb + (size_t)x_cat[n] * DD + q * 4);
    float4 o;
    o.x = a.x + b.x; o.y = a.y + b.y; o.z = a.z + b.z; o.w = a.w + b.w;
    *reinterpret_cast<float4*>(g_h0 + (size_t)idx * 4) = o;
}

// ---------------- fused transform GEMM ----------------
// C[n, 0:256]  = relu_in(hin[n]) @ Wcat  -> g_transb (bf16x2)
// C[n,256:320] = relu_in(hin[n]) @ root + bias -> hout (fp32 accumulator init)

#define SMEM_GEMM (64 * 320 * 4 + 64 * 64 * 8)   // sW 80KB + sAdup 32KB = 112KB

static __device__ __forceinline__ void ffma2(unsigned long long& acc,
                                             unsigned long long a, unsigned long long b) {
    asm("fma.rn.f32x2 %0, %1, %2, %0;" : "+l"(acc) : "l"(a), "l"(b));
}

__global__ void __launch_bounds__(512, 1)
k_trans(const float* __restrict__ hin,
        const float* __restrict__ w, const float* __restrict__ root,
        const float* __restrict__ bias,
        float* __restrict__ hout, int relu_in) {
    extern __shared__ float sm[];
    float* sW = sm;                                        // [64][320]
    unsigned long long* sA = (unsigned long long*)(sm + 64 * 320);  // [64][64] dup pairs
    int tid = threadIdx.x;
    int n0 = blockIdx.x * 64;

    // stage W: sW[k][r*64+j] = w[r,k,j]; sW[k][256+j] = root[k,j]
    for (int i = tid; i < 64 * 80; i += 512) {
        int k = i / 80, c4 = (i % 80) * 4;
        float4 v;
        if (c4 < 256) {
            int r = c4 >> 6, j = c4 & 63;
            v = ld4(w + (size_t)r * 4096 + k * 64 + j);
        } else {
            v = ld4(root + (size_t)k * 64 + (c4 - 256));
        }
        *reinterpret_cast<float4*>(&sW[k * 320 + c4]) = v;
    }
    // stage A duplicated: sA[n][k] = {a, a}
    for (int i = tid; i < 64 * 64; i += 512) {
        int nl = i >> 6, k = i & 63;
        float a = hin[(size_t)(n0 + nl) * 64 + k];
        if (relu_in) a = fmaxf(a, 0.f);
        unsigned long long aa;
        asm("mov.b64 %0, {%1, %1};" : "=l"(aa) : "f"(a));
        sA[nl * 64 + k] = aa;
    }
    __syncthreads();

    int c  = tid & 15;
    int nz = tid >> 4;                                     // 0..31
    const unsigned long long* sW64 = (const unsigned long long*)sW;  // [64][160]

    unsigned long long acc[2][10];
#pragma unroll
    for (int i = 0; i < 2; i++)
#pragma unroll
        for (int p = 0; p < 10; p++) acc[i][p] = 0ull;

#pragma unroll 4
    for (int k = 0; k < 64; k++) {
        unsigned long long b[10];
#pragma unroll
        for (int p = 0; p < 10; p++) b[p] = sW64[k * 160 + c + p * 16];
#pragma unroll
        for (int i = 0; i < 2; i++) {
            unsigned long long a = sA[(nz * 2 + i) * 64 + k];
#pragma unroll
            for (int p = 0; p < 10; p++) ffma2(acc[i][p], a, b[p]);
        }
    }

#pragma unroll
    for (int i = 0; i < 2; i++) {
        int n = n0 + nz * 2 + i;
#pragma unroll
        for (int p = 0; p < 10; p++) {
            float2 f;
            asm("mov.b64 {%0, %1}, %2;" : "=f"(f.x), "=f"(f.y) : "l"(acc[i][p]));
            if (p < 8) {
                // pair index c+16p in [0,128): bf16x2 {lo=even col, hi=odd col}
                unsigned u;
                asm("cvt.rn.bf16x2.f32 %0, %1, %2;" : "=r"(u) : "f"(f.y), "f"(f.x));
                g_transb[(size_t)n * 128 + c + p * 16] = u;
            } else {
                int j = 2 * c + 32 * (p - 8);
                f.x += bias[j]; f.y += bias[j + 1];
                *reinterpret_cast<float2*>(hout + (size_t)n * 64 + j) = f;
            }
        }
    }
}

// ---------------- CSR gather: hout[t] += sum_r inv[t,r] * sum_e trans[src_e, r] ----------------
// One warp per node; lane owns column pair (2*lane, 2*lane+1).
// esrc chunk loaded coalesced 32-wide then shfl-broadcast; trans loads 4-deep pipelined.

static __device__ __forceinline__ void acc_bf2(float2& a, unsigned v) {
    a.x += __uint_as_float(v << 16);
    a.y += __uint_as_float(v & 0xffff0000u);
}

__global__ void __launch_bounds__(256)
k_gather(float* __restrict__ hout) {
    int t = blockIdx.x * 8 + (threadIdx.x >> 5);   // 25000*8 == NN exactly
    int lane = threadIdx.x & 31;
    const unsigned F = 0xffffffffu;
    float2 tot = {0.f, 0.f};

#pragma unroll
    for (int r = 0; r < RR; r++) {
        int b = t * RR + r;
        int cnt = __ldg(&g_cnt[b]);
        if (cnt == 0) continue;                    // warp-uniform
        int start = __ldg(&g_off[b]);
        float2 a0 = {0.f,0.f}, a1 = {0.f,0.f}, a2 = {0.f,0.f}, a3 = {0.f,0.f};
        for (int base = 0; base < cnt; base += 32) {
            int m = min(32, cnt - base);
            int sv = 0;
            if (lane < m) sv = __ldg(&g_esrc[start + base + lane]);
            int j = 0;
            for (; j + 4 <= m; j += 4) {
                int s0 = __shfl_sync(F, sv, j);
                int s1 = __shfl_sync(F, sv, j + 1);
                int s2 = __shfl_sync(F, sv, j + 2);
                int s3 = __shfl_sync(F, sv, j + 3);
                unsigned v0 = __ldg(&g_transb[((size_t)s0 * RR + r) * 32 + lane]);
                unsigned v1 = __ldg(&g_transb[((size_t)s1 * RR + r) * 32 + lane]);
                unsigned v2 = __ldg(&g_transb[((size_t)s2 * RR + r) * 32 + lane]);
                unsigned v3 = __ldg(&g_transb[((size_t)s3 * RR + r) * 32 + lane]);
                acc_bf2(a0, v0); acc_bf2(a1, v1); acc_bf2(a2, v2); acc_bf2(a3, v3);
            }
            for (; j < m; j++) {
                int s = __shfl_sync(F, sv, j);
                unsigned v = __ldg(&g_transb[((size_t)s * RR + r) * 32 + lane]);
                acc_bf2(a0, v);
            }
        }
        float sc = __ldg(&g_inv[b]);
        tot.x += ((a0.x + a1.x) + (a2.x + a3.x)) * sc;
        tot.y += ((a0.y + a1.y) + (a2.y + a3.y)) * sc;
    }

    float2* hp = reinterpret_cast<float2*>(hout + (size_t)t * DD) + lane;
    float2 cur = *hp;
    cur.x += tot.x; cur.y += tot.y;
    *hp = cur;
}

// ---------------- mean pool (batch is sorted) ----------------

__global__ void k_pool(const float* __restrict__ h, const int* __restrict__ batch) {
    int d = threadIdx.x;                         // 64
    int row = threadIdx.y;                       // 4
    int base = (blockIdx.x * 4 + row) * 512;
    int gcur = -1;
    float acc = 0.f;
    for (int i = 0; i < 512; i++) {
        int n = base + i;
        if (n >= NN) break;
        int g = __ldg(batch + n);
        if (g != gcur) {
            if (gcur >= 0) atomicAdd(&g_pool[gcur * DD + d], acc);
            acc = 0.f; gcur = g;
        }
        acc += h[(size_t)n * DD + d];
    }
    if (gcur >= 0) atomicAdd(&g_pool[gcur * DD + d], acc);
}

// ---------------- head: fc1+relu, fc2, log_softmax ----------------

__global__ void k_head(const float* __restrict__ fc1w, const float* __restrict__ fc1b,
                       const float* __restrict__ fc2w, const float* __restrict__ fc2b,
                       float* __restrict__ out) {
    int g = blockIdx.x;
    int tid = threadIdx.x;   // 64
    __shared__ float p[64], t[64], lg[10], lse;
    p[tid] = g_pool[g * DD + tid] * g_binv[g];
    __syncthreads();
    float s = fc1b[tid];
#pragma unroll 8
    for (int k = 0; k < 64; k++) s += p[k] * fc1w[k * 64 + tid];
    t[tid] = fmaxf(s, 0.f);
    __syncthreads();
    if (tid < CC) {
        float s2 = fc2b[tid];
#pragma unroll 8
        for (int k = 0; k < 64; k++) s2 += t[k] * fc2w[k * CC + tid];
        lg[tid] = s2;
    }
    __syncthreads();
    if (tid == 0) {
        float m = lg[0];
        for (int c2 = 1; c2 < CC; c2++) m = fmaxf(m, lg[c2]);
        float se = 0.f;
        for (int c2 = 0; c2 < CC; c2++) se += expf(lg[c2] - m);
        lse = m + logf(se);
    }
    __syncthreads();
    if (tid < CC) out[g * CC + tid] = lg[tid] - lse;
}

// ---------------- launch ----------------

extern "C" void kernel_launch(void* const* d_in, const int* in_sizes, int n_in,
                              void* d_out, int out_size) {
    const int*   x_op    = (const int*)d_in[0];
    const int*   x_cat   = (const int*)d_in[1];
    const int*   eidx    = (const int*)d_in[2];
    const int*   etype   = (const int*)d_in[3];
    const int*   batch   = (const int*)d_in[4];
    const float* op_emb  = (const float*)d_in[5];
    const float* cat_emb = (const float*)d_in[6];
    const float* W[3]    = { (const float*)d_in[7],  (const float*)d_in[10], (const float*)d_in[13] };
    const float* Rt[3]   = { (const float*)d_in[8],  (const float*)d_in[11], (const float*)d_in[14] };
    const float* B[3]    = { (const float*)d_in[9],  (const float*)d_in[12], (const float*)d_in[15] };
    const float* fc1w    = (const float*)d_in[16];
    const float* fc1b    = (const float*)d_in[17];
    const float* fc2w    = (const float*)d_in[18];
    const float* fc2b    = (const float*)d_in[19];
    float* out = (float*)d_out;

    const int* src = eidx;
    const int* tgt = eidx + EE;

    void *p_cnt, *p_fcnt, *p_total, *p_bcnt, *p_pool, *p0, *p1;
    cudaGetSymbolAddress(&p_cnt, g_cnt);
    cudaGetSymbolAddress(&p_fcnt, g_fcnt);
    cudaGetSymbolAddress(&p_total, g_total);
    cudaGetSymbolAddress(&p_bcnt, g_bcnt);
    cudaGetSymbolAddress(&p_pool, g_pool);
    cudaGetSymbolAddress(&p0, g_h0);
    cudaGetSymbolAddress(&p1, g_h1);
    float* hbuf[2] = { (float*)p0, (float*)p1 };

    cudaFuncSetAttribute(k_trans, cudaFuncAttributeMaxDynamicSharedMemorySize, SMEM_GEMM);

    cudaMemsetAsync(p_cnt, 0, sizeof(int) * NN * RR, 0);
    cudaMemsetAsync(p_fcnt, 0, sizeof(int) * NN * RR, 0);
    cudaMemsetAsync(p_total, 0, sizeof(int), 0);
    cudaMemsetAsync(p_bcnt, 0, sizeof(int) * GG, 0);
    cudaMemsetAsync(p_pool, 0, sizeof(float) * GG * DD, 0);

    // CSR build (once per launch; reused by all 3 layers)
    k_count_edges<<<(EE + 255) / 256, 256>>>(tgt, etype);
    k_count_batch<<<(NN + 255) / 256, 256>>>(batch);
    k_offsets<<<(NN * RR) / 256, 256>>>();
    k_fill<<<(EE + 255) / 256, 256>>>(src, tgt, etype);
    k_invert<<<(NN * RR + 255) / 256, 256>>>();
    k_embed<<<(NN * 16 + 255) / 256, 256>>>(x_op, x_cat, op_emb, cat_emb);

    for (int l = 0; l < 3; l++) {
        const float* hin = hbuf[l & 1];
        float* hout = hbuf[(l + 1) & 1];
        // GEMM writes bf16 g_transb AND initializes hout with root transform + bias
        k_trans<<<NN / 64, 512, SMEM_GEMM>>>(hin, W[l], Rt[l], B[l], hout, l > 0 ? 1 : 0);
        // CSR gather accumulates mean-scaled messages into hout (no atomics)
        k_gather<<<NN / 8, 256>>>(hout);
    }

    k_pool<<<(NN + 2047) / 2048, dim3(64, 4)>>>(hbuf[1], batch);
    k_head<<<GG, 64>>>(fc1w, fc1b, fc2w, fc2b, out);
}